// round 12
// baseline (speedup 1.0000x reference)
#include <cuda_runtime.h>
#include <cstdint>
#include <math.h>

#define BATCH 16
#define CCH   256
#define LSEQ  2048
#define BM    64
#define BN    64
#define NTILES 32
#define NTHREADS 512   // 16 warps

#define QS_STRIDE 260          // A-frag bank 4g+tig (bijective)
#define KV_STRIDE 72           // B-frag bank 8tig+g / 8g+tig (bijective)
#define SS_STRIDE 68           // bank 4g+tig
#define QS_FLOATS (BM * QS_STRIDE)    // 16640
#define KV_FLOATS (CCH * KV_STRIDE)   // 18432 (x2: K and V)
#define SS_FLOATS (BM * SS_STRIDE)    // 4352
#define SMEM_FLOATS (QS_FLOATS + 2 * KV_FLOATS + SS_FLOATS + 3 * 64)
#define SMEM_BYTES  (SMEM_FLOATS * 4) // 232,192 <= 232,448

__device__ __forceinline__ unsigned tf32b(float x) {
    unsigned u; asm("cvt.rna.tf32.f32 %0, %1;" : "=r"(u) : "f"(x));
    return u;
}
__device__ __forceinline__ float to_tf32(float x) { return __uint_as_float(tf32b(x)); }

__device__ __forceinline__ void mma_tf32(float d[4], const float a[4], const float b[2]) {
    const unsigned* A = reinterpret_cast<const unsigned*>(a);
    const unsigned* B = reinterpret_cast<const unsigned*>(b);
    asm volatile(
        "mma.sync.aligned.m16n8k8.row.col.f32.tf32.tf32.f32 "
        "{%0,%1,%2,%3}, {%4,%5,%6,%7}, {%8,%9}, {%0,%1,%2,%3};\n"
        : "+f"(d[0]), "+f"(d[1]), "+f"(d[2]), "+f"(d[3])
        : "r"(A[0]), "r"(A[1]), "r"(A[2]), "r"(A[3]), "r"(B[0]), "r"(B[1]));
}

__global__ void __launch_bounds__(NTHREADS, 1)
attn_pf_kernel(const float* __restrict__ Q, const float* __restrict__ K,
               const float* __restrict__ V, const float* __restrict__ Mask,
               float* __restrict__ Out) {
    extern __shared__ float smem[];
    float* Qs    = smem;                  // [64][260] (l,c) tf32, *1/16
    float* Ks    = Qs + QS_FLOATS;        // [256][72] (c,m)
    float* Vs    = Ks + KV_FLOATS;        // [256][72] (c,m)
    float* Ss    = Vs + KV_FLOATS;        // [64][68]  (l,m): S then P
    float* maskT = Ss + SS_FLOATS;        // [64]
    float* lmT   = maskT + 64;            // [64]
    float* Drow  = lmT + 64;              // [64]

    const int tid = threadIdx.x, w = tid >> 5, lane = tid & 31;
    const int g = lane >> 2, tig = lane & 3;
    const int b = blockIdx.y, l0 = blockIdx.x * BM;

    const float* Qb = Q + (size_t)b * CCH * LSEQ;
    const float* Kb = K + (size_t)b * CCH * LSEQ;
    const float* Vb = V + (size_t)b * CCH * LSEQ;
    const float* Mb = Mask + (size_t)b * LSEQ;

    // staging map: c = tid>>1 is wrong for 512 thr; use idx = i*512+tid, c=idx>>4, j=idx&15
    // ---- stage Q once: Qs[l][c] = tf32(Q[b][c][l0+l]/16) ----
    {
        const float s16 = 0.0625f;
        #pragma unroll
        for (int i = 0; i < 8; i++) {
            int idx = i * NTHREADS + tid;
            int c = idx >> 4, j = idx & 15;
            float4 v = *reinterpret_cast<const float4*>(Qb + (size_t)c * LSEQ + l0 + 4 * j);
            Qs[(4 * j + 0) * QS_STRIDE + c] = to_tf32(v.x * s16);
            Qs[(4 * j + 1) * QS_STRIDE + c] = to_tf32(v.y * s16);
            Qs[(4 * j + 2) * QS_STRIDE + c] = to_tf32(v.z * s16);
            Qs[(4 * j + 3) * QS_STRIDE + c] = to_tf32(v.w * s16);
        }
    }
    // ---- stage K[0] + mask[0] ----
    #pragma unroll
    for (int i = 0; i < 8; i++) {
        int idx = i * NTHREADS + tid;
        int c = idx >> 4, j = idx & 15;
        float4 v = *reinterpret_cast<const float4*>(Kb + (size_t)c * LSEQ + 4 * j);
        v.x = to_tf32(v.x); v.y = to_tf32(v.y); v.z = to_tf32(v.z); v.w = to_tf32(v.w);
        *reinterpret_cast<float4*>(&Ks[c * KV_STRIDE + 4 * j]) = v;
    }
    if (tid < 64) {
        float mk = Mb[tid];
        maskT[tid] = mk;
        lmT[tid] = __logf(mk + 1e-9f);
    }

    const int R0 = 16 * (w & 3);    // S rows
    const int C0 = 16 * (w >> 2);   // S cols
    const int Cw = 16 * w;          // PV channels

    float O[4][2][4];
    #pragma unroll
    for (int mt = 0; mt < 4; mt++)
        #pragma unroll
        for (int nt = 0; nt < 2; nt++)
            #pragma unroll
            for (int r = 0; r < 4; r++) O[mt][nt][r] = 0.0f;

    const int sr = tid >> 3;        // softmax row
    const int cq = (tid & 7) * 8;   // softmax col base
    float den = 0.0f;

    __syncthreads();

    for (int t = 0; t < NTILES; t++) {
        const int m0 = t * BN;
        // (entry: K[t], mask[t] staged & visible)

        // ---- issue V[t] prefetch LDGs (land during S-GEMM) ----
        float4 vreg[8];
        {
            int c = tid >> 1;                  // 0..255
            int jb = (tid & 1) * 8;            // float4 col base: 0 or 8
            #pragma unroll
            for (int i = 0; i < 8; i++)
                vreg[i] = *reinterpret_cast<const float4*>(Vb + (size_t)c * LSEQ + m0 + 4 * (jb + i));
        }

        // ---- S = (Q/16)^T K, warp tile 16x16, K-dim 256 ----
        {
            float sacc[2][4];
            #pragma unroll
            for (int nt = 0; nt < 2; nt++)
                #pragma unroll
                for (int r = 0; r < 4; r++) sacc[nt][r] = 0.0f;

            const float* qr0 = &Qs[(R0 + g) * QS_STRIDE];
            const float* qr1 = qr0 + 8 * QS_STRIDE;
            #pragma unroll 8
            for (int k0 = 0; k0 < CCH; k0 += 8) {
                float a[4];
                a[0] = qr0[k0 + tig];
                a[1] = qr1[k0 + tig];
                a[2] = qr0[k0 + tig + 4];
                a[3] = qr1[k0 + tig + 4];
                const float* bp0 = &Ks[(k0 + tig) * KV_STRIDE + C0 + g];
                const float* bp1 = bp0 + 4 * KV_STRIDE;
                #pragma unroll
                for (int nt = 0; nt < 2; nt++) {
                    float bb[2] = { bp0[8 * nt], bp1[8 * nt] };
                    mma_tf32(sacc[nt], a, bb);
                }
            }
            #pragma unroll
            for (int nt = 0; nt < 2; nt++) {
                int col = C0 + 8 * nt + 2 * tig;
                float* p0 = &Ss[(R0 + g) * SS_STRIDE + col];
                float* p1 = p0 + 8 * SS_STRIDE;
                p0[0] = sacc[nt][0]; p0[1] = sacc[nt][1];
                p1[0] = sacc[nt][2]; p1[1] = sacc[nt][3];
            }
        }
        __syncthreads();   // S visible; K[t] no longer needed

        // ---- STS V[t] from prefetch regs ----
        {
            int c = tid >> 1;
            int jb = (tid & 1) * 8;
            #pragma unroll
            for (int i = 0; i < 8; i++) {
                float4 v = vreg[i];
                v.x = to_tf32(v.x); v.y = to_tf32(v.y); v.z = to_tf32(v.z); v.w = to_tf32(v.w);
                *reinterpret_cast<float4*>(&Vs[c * KV_STRIDE + 4 * (jb + i)]) = v;
            }
        }

        // ---- issue K[t+1] prefetch LDGs + mask[t+1] (land during PV) ----
        float4 kreg[8];
        float mk1 = 0.0f, lm1 = 0.0f;
        if (t + 1 < NTILES) {
            int c = tid >> 1;
            int jb = (tid & 1) * 8;
            #pragma unroll
            for (int i = 0; i < 8; i++)
                kreg[i] = *reinterpret_cast<const float4*>(Kb + (size_t)c * LSEQ + m0 + BN + 4 * (jb + i));
            if (tid < 64) {
                mk1 = Mb[m0 + BN + tid];
                lm1 = __logf(mk1 + 1e-9f);
            }
        }

        // ---- softmax (no max-subtraction; logits bounded): thread owns (row, 8 cols) ----
        {
            float* pw = &Ss[sr * SS_STRIDE + cq];
            const float* lmp = &lmT[cq];
            const float* mp  = &maskT[cq];
            #pragma unroll
            for (int j = 0; j < 8; j++) {
                float e = __expf(pw[j] + lmp[j]);
                den += e;
                pw[j] = __uint_as_float(tf32b(e * mp[j]));
            }
        }
        __syncthreads();   // P, V visible; maskT[t] consumed

        // ---- O += V * P^T (K-dim 64), 16 channels/warp ----
        #pragma unroll
        for (int k0 = 0; k0 < BN; k0 += 8) {
            float bb[2][2];
            #pragma unroll
            for (int nt = 0; nt < 2; nt++) {
                const float* vp = &Vs[(Cw + 8 * nt + g) * KV_STRIDE + k0 + tig];
                bb[nt][0] = vp[0];
                bb[nt][1] = vp[4];
            }
            #pragma unroll
            for (int mt = 0; mt < 4; mt++) {
                const float* pr0 = &Ss[(16 * mt + g) * SS_STRIDE + k0 + tig];
                const float* pr1 = pr0 + 8 * SS_STRIDE;
                float a[4] = { pr0[0], pr1[0], pr0[4], pr1[4] };
                #pragma unroll
                for (int nt = 0; nt < 2; nt++) mma_tf32(O[mt][nt], a, bb[nt]);
            }
        }

        // ---- STS K[t+1] + mask[t+1] (K buffer idle since post-S-GEMM) ----
        if (t + 1 < NTILES) {
            int c = tid >> 1;
            int jb = (tid & 1) * 8;
            #pragma unroll
            for (int i = 0; i < 8; i++) {
                float4 v = kreg[i];
                v.x = to_tf32(v.x); v.y = to_tf32(v.y); v.z = to_tf32(v.z); v.w = to_tf32(v.w);
                *reinterpret_cast<float4*>(&Ks[c * KV_STRIDE + 4 * (jb + i)]) = v;
            }
            if (tid < 64) {
                maskT[tid] = mk1;
                lmT[tid] = lm1;
            }
        }
        __syncthreads();   // K[t+1]/mask visible; P buffer free for next S
    }

    // ---- reduce denominators (8 threads per row) ----
    den += __shfl_xor_sync(0xffffffffu, den, 1);
    den += __shfl_xor_sync(0xffffffffu, den, 2);
    den += __shfl_xor_sync(0xffffffffu, den, 4);
    if ((tid & 7) == 0) Drow[sr] = den;
    __syncthreads();

    // ---- epilogue: O/den, transpose via smem (reuse Qs), coalesced stores ----
    float* T = Qs + w * 1040;   // 16 ch x 64 l, stride 65
    #pragma unroll
    for (int mt = 0; mt < 4; mt++) {
        float inv0 = 1.0f / Drow[16 * mt + g];
        float inv1 = 1.0f / Drow[16 * mt + 8 + g];
        #pragma unroll
        for (int nt = 0; nt < 2; nt++) {
            int c2 = 8 * nt + 2 * tig;
            T[(c2    ) * 65 + 16 * mt + g    ] = O[mt][nt][0] * inv0;
            T[(c2 + 1) * 65 + 16 * mt + g    ] = O[mt][nt][1] * inv0;
            T[(c2    ) * 65 + 16 * mt + g + 8] = O[mt][nt][2] * inv1;
            T[(c2 + 1) * 65 + 16 * mt + g + 8] = O[mt][nt][3] * inv1;
        }
    }
    __syncwarp();
    float* outw = Out + ((size_t)b * CCH + Cw) * LSEQ + l0;
    #pragma unroll 4
    for (int cl = 0; cl < 16; cl++) {
        float* orow = outw + (size_t)cl * LSEQ;
        orow[lane]      = T[cl * 65 + lane];
        orow[lane + 32] = T[cl * 65 + 32 + lane];
    }
}

extern "C" void kernel_launch(void* const* d_in, const int* in_sizes, int n_in,
                              void* d_out, int out_size) {
    (void)in_sizes; (void)n_in; (void)out_size;
    const float* Q = (const float*)d_in[0];
    const float* K = (const float*)d_in[1];
    const float* V = (const float*)d_in[2];
    const float* M = (const float*)d_in[3];
    float* O = (float*)d_out;

    cudaFuncSetAttribute(attn_pf_kernel,
                         cudaFuncAttributeMaxDynamicSharedMemorySize, SMEM_BYTES);
    dim3 grid(LSEQ / BM, BATCH);   // 32 x 16 = 512 CTAs
    attn_pf_kernel<<<grid, NTHREADS, SMEM_BYTES>>>(Q, K, V, M, O);
}

// round 13
// speedup vs baseline: 1.5527x; 1.5527x over previous
#include <cuda_runtime.h>
#include <cstdint>
#include <math.h>

#define BATCH 16
#define CCH   256
#define LSEQ  2048
#define BM    32       // query rows per CTA
#define BN    64       // kv columns per tile
#define NTILES 32
#define NTHREADS 256   // 8 warps, 2 CTAs/SM

#define QS_STRIDE 260          // A-frag bank 4g+tig (bijective)
#define KV_STRIDE 68           // S-B bank 4tig+g, PV-B bank 4g+tig (bijective)
#define SS_STRIDE 68           // bank 4g+tig
#define QS_FLOATS (BM * QS_STRIDE)    // 8320
#define KV_FLOATS (CCH * KV_STRIDE)   // 17408
#define SS_FLOATS (BM * SS_STRIDE)    // 2176
#define SMEM_FLOATS (QS_FLOATS + KV_FLOATS + SS_FLOATS + 160)
#define SMEM_BYTES  (SMEM_FLOATS * 4) // 112,256 B -> 2 CTAs = 224,512 <= 233,472

__device__ __forceinline__ unsigned tf32b(float x) {
    unsigned u; asm("cvt.rna.tf32.f32 %0, %1;" : "=r"(u) : "f"(x));
    return u;
}
__device__ __forceinline__ float to_tf32(float x) { return __uint_as_float(tf32b(x)); }

__device__ __forceinline__ void mma_tf32(float d[4], const float a[4], const float b[2]) {
    const unsigned* A = reinterpret_cast<const unsigned*>(a);
    const unsigned* B = reinterpret_cast<const unsigned*>(b);
    asm volatile(
        "mma.sync.aligned.m16n8k8.row.col.f32.tf32.tf32.f32 "
        "{%0,%1,%2,%3}, {%4,%5,%6,%7}, {%8,%9}, {%0,%1,%2,%3};\n"
        : "+f"(d[0]), "+f"(d[1]), "+f"(d[2]), "+f"(d[3])
        : "r"(A[0]), "r"(A[1]), "r"(A[2]), "r"(A[3]), "r"(B[0]), "r"(B[1]));
}

__global__ void __launch_bounds__(NTHREADS, 2)
attn2c_kernel(const float* __restrict__ Q, const float* __restrict__ K,
              const float* __restrict__ V, const float* __restrict__ Mask,
              float* __restrict__ Out) {
    extern __shared__ float smem[];
    float* Qs    = smem;                  // [32][260] (l,c) tf32, *1/16
    float* KVs   = Qs + QS_FLOATS;        // [256][68] (c,m): K then V
    float* Ss    = KVs + KV_FLOATS;       // [32][68]  (l,m): S then P
    float* maskT = Ss + SS_FLOATS;        // [64]
    float* lmT   = maskT + 64;            // [64]
    float* Drow  = lmT + 64;              // [32]

    const int tid = threadIdx.x, w = tid >> 5, lane = tid & 31;
    const int g = lane >> 2, tig = lane & 3;
    const int b = blockIdx.y, l0 = blockIdx.x * BM;

    const float* Qb = Q + (size_t)b * CCH * LSEQ;
    const float* Kb = K + (size_t)b * CCH * LSEQ;
    const float* Vb = V + (size_t)b * CCH * LSEQ;
    const float* Mb = Mask + (size_t)b * LSEQ;

    // ---- stage Q once: Qs[l][c] = tf32(Q[b][c][l0+l]/16) ----
    {
        const float s16 = 0.0625f;
        #pragma unroll
        for (int i = 0; i < 8; i++) {
            int idx = i * NTHREADS + tid;   // 0..2047
            int c = idx >> 3, j = idx & 7;
            float4 v = *reinterpret_cast<const float4*>(Qb + (size_t)c * LSEQ + l0 + 4 * j);
            Qs[(4 * j + 0) * QS_STRIDE + c] = to_tf32(v.x * s16);
            Qs[(4 * j + 1) * QS_STRIDE + c] = to_tf32(v.y * s16);
            Qs[(4 * j + 2) * QS_STRIDE + c] = to_tf32(v.z * s16);
            Qs[(4 * j + 3) * QS_STRIDE + c] = to_tf32(v.w * s16);
        }
    }

    // S-GEMM: 2x4 grid of 16x16 warp tiles over S[32][64]
    const int R0 = 16 * (w & 1);
    const int C0 = 16 * (w >> 1);
    // PV: each warp 32 rows x 32 channels
    const int Cw = 32 * w;

    float O[2][4][4];
    #pragma unroll
    for (int mt = 0; mt < 2; mt++)
        #pragma unroll
        for (int nt = 0; nt < 4; nt++)
            #pragma unroll
            for (int r = 0; r < 4; r++) O[mt][nt][r] = 0.0f;

    const int sr = tid >> 3;        // softmax row (0..31)
    const int cq = (tid & 7) * 8;   // softmax col base
    float den = 0.0f;

    __syncthreads();

    for (int t = 0; t < NTILES; t++) {
        const int m0 = t * BN;

        // ---- stage K tile: KVs[c][m] ----
        #pragma unroll
        for (int i = 0; i < 16; i++) {
            int idx = i * NTHREADS + tid;   // 0..4095
            int c = idx >> 4, j = idx & 15;
            float4 v = *reinterpret_cast<const float4*>(Kb + (size_t)c * LSEQ + m0 + 4 * j);
            v.x = to_tf32(v.x); v.y = to_tf32(v.y); v.z = to_tf32(v.z); v.w = to_tf32(v.w);
            *reinterpret_cast<float4*>(&KVs[c * KV_STRIDE + 4 * j]) = v;
        }
        if (tid < 64) {
            float mk = Mb[m0 + tid];
            maskT[tid] = mk;
            lmT[tid] = __logf(mk + 1e-9f);
        }
        __syncthreads();

        // ---- S = (Q/16)^T K, warp tile 16x16, K-dim 256 ----
        {
            float sacc[2][4];
            #pragma unroll
            for (int nt = 0; nt < 2; nt++)
                #pragma unroll
                for (int r = 0; r < 4; r++) sacc[nt][r] = 0.0f;

            const float* qr0 = &Qs[(R0 + g) * QS_STRIDE];
            const float* qr1 = qr0 + 8 * QS_STRIDE;
            #pragma unroll 8
            for (int k0 = 0; k0 < CCH; k0 += 8) {
                float a[4];
                a[0] = qr0[k0 + tig];
                a[1] = qr1[k0 + tig];
                a[2] = qr0[k0 + tig + 4];
                a[3] = qr1[k0 + tig + 4];
                const float* bp0 = &KVs[(k0 + tig) * KV_STRIDE + C0 + g];
                const float* bp1 = bp0 + 4 * KV_STRIDE;
                #pragma unroll
                for (int nt = 0; nt < 2; nt++) {
                    float bb[2] = { bp0[8 * nt], bp1[8 * nt] };
                    mma_tf32(sacc[nt], a, bb);
                }
            }
            #pragma unroll
            for (int nt = 0; nt < 2; nt++) {
                int col = C0 + 8 * nt + 2 * tig;
                float* p0 = &Ss[(R0 + g) * SS_STRIDE + col];
                float* p1 = p0 + 8 * SS_STRIDE;
                p0[0] = sacc[nt][0]; p0[1] = sacc[nt][1];
                p1[0] = sacc[nt][2]; p1[1] = sacc[nt][3];
            }
        }
        __syncthreads();   // S visible; K no longer needed

        // ---- stage V (overwrites K) ----
        #pragma unroll
        for (int i = 0; i < 16; i++) {
            int idx = i * NTHREADS + tid;
            int c = idx >> 4, j = idx & 15;
            float4 v = *reinterpret_cast<const float4*>(Vb + (size_t)c * LSEQ + m0 + 4 * j);
            v.x = to_tf32(v.x); v.y = to_tf32(v.y); v.z = to_tf32(v.z); v.w = to_tf32(v.w);
            *reinterpret_cast<float4*>(&KVs[c * KV_STRIDE + 4 * j]) = v;
        }

        // ---- softmax (no max-subtraction; logits bounded ~6) ----
        {
            float* pw = &Ss[sr * SS_STRIDE + cq];
            const float* lmp = &lmT[cq];
            const float* mp  = &maskT[cq];
            #pragma unroll
            for (int j = 0; j < 8; j++) {
                float e = __expf(pw[j] + lmp[j]);
                den += e;
                pw[j] = __uint_as_float(tf32b(e * mp[j]));
            }
        }
        __syncthreads();   // P, V visible

        // ---- O += V * P^T (K-dim 64), warp: 32 rows x 32 channels ----
        #pragma unroll
        for (int k0 = 0; k0 < BN; k0 += 8) {
            float bb[4][2];
            #pragma unroll
            for (int nt = 0; nt < 4; nt++) {
                const float* vp = &KVs[(Cw + 8 * nt + g) * KV_STRIDE + k0 + tig];
                bb[nt][0] = vp[0];
                bb[nt][1] = vp[4];
            }
            #pragma unroll
            for (int mt = 0; mt < 2; mt++) {
                const float* pr0 = &Ss[(16 * mt + g) * SS_STRIDE + k0 + tig];
                const float* pr1 = pr0 + 8 * SS_STRIDE;
                float a[4] = { pr0[0], pr1[0], pr0[4], pr1[4] };
                #pragma unroll
                for (int nt = 0; nt < 4; nt++) mma_tf32(O[mt][nt], a, bb[nt]);
            }
        }
        __syncthreads();   // V/S buffers free for next tile
    }

    // ---- reduce denominators (8 threads per row) ----
    den += __shfl_xor_sync(0xffffffffu, den, 1);
    den += __shfl_xor_sync(0xffffffffu, den, 2);
    den += __shfl_xor_sync(0xffffffffu, den, 4);
    if ((tid & 7) == 0) Drow[sr] = den;
    __syncthreads();

    // ---- epilogue: O/den, transpose via smem (reuse Q/KV region), coalesced stores ----
    float* T = smem + w * 1056;   // 32 ch x 32 l, stride 33
    #pragma unroll
    for (int mt = 0; mt < 2; mt++) {
        float inv0 = 1.0f / Drow[16 * mt + g];
        float inv1 = 1.0f / Drow[16 * mt + 8 + g];
        #pragma unroll
        for (int nt = 0; nt < 4; nt++) {
            int c2 = 8 * nt + 2 * tig;
            int rl = 16 * mt + g;
            T[(c2    ) * 33 + rl    ] = O[mt][nt][0] * inv0;
            T[(c2 + 1) * 33 + rl    ] = O[mt][nt][1] * inv0;
            T[(c2    ) * 33 + rl + 8] = O[mt][nt][2] * inv1;
            T[(c2 + 1) * 33 + rl + 8] = O[mt][nt][3] * inv1;
        }
    }
    __syncwarp();
    float* outw = Out + ((size_t)b * CCH + Cw) * LSEQ + l0;
    #pragma unroll 4
    for (int cl = 0; cl < 32; cl++)
        outw[(size_t)cl * LSEQ + lane] = T[cl * 33 + lane];
}

extern "C" void kernel_launch(void* const* d_in, const int* in_sizes, int n_in,
                              void* d_out, int out_size) {
    (void)in_sizes; (void)n_in; (void)out_size;
    const float* Q = (const float*)d_in[0];
    const float* K = (const float*)d_in[1];
    const float* V = (const float*)d_in[2];
    const float* M = (const float*)d_in[3];
    float* O = (float*)d_out;

    cudaFuncSetAttribute(attn2c_kernel,
                         cudaFuncAttributeMaxDynamicSharedMemorySize, SMEM_BYTES);
    dim3 grid(LSEQ / BM, BATCH);   // 64 x 16 = 1024 CTAs, 2 per SM
    attn2c_kernel<<<grid, NTHREADS, SMEM_BYTES>>>(Q, K, V, M, O);
}

// round 14
// speedup vs baseline: 2.6098x; 1.6808x over previous
#include <cuda_runtime.h>
#include <cuda_fp16.h>
#include <cstdint>
#include <math.h>

#define BATCH 16
#define CCH   256
#define LSEQ  2048
#define BM    64
#define BN    64
#define NTILES 32
#define NTHREADS 512   // 16 warps

// strides (in elements)
#define QSH 264   // Qs halves/row  (264/8=33 odd -> ldmatrix conflict-free)
#define KVH 72    // Ks/Vs halves/row (72/8=9 odd)
#define PSH 72    // Ps halves/row
#define SSF 68    // Ss floats/row

// byte offsets in dynamic smem
#define QS_B   0                         // 64*264*2   = 33792
#define KS_B   33792                     // 256*72*2   = 36864
#define VS_B   70656                     // 256*72*2   = 36864
#define SS_B   107520                    // 64*68*4    = 17408
#define PS_B   124928                    // 64*72*2    = 9216
#define MASK_B 134144                    // 64*4
#define LM_B   134400                    // 64*4
#define DROW_B 134656                    // 64*4
#define SMEM_BYTES 134912

#define LDSM_X4(r0,r1,r2,r3,addr) \
    asm volatile("ldmatrix.sync.aligned.m8n8.x4.shared.b16 {%0,%1,%2,%3}, [%4];" \
        : "=r"(r0),"=r"(r1),"=r"(r2),"=r"(r3) : "r"(addr))
#define LDSM_X4T(r0,r1,r2,r3,addr) \
    asm volatile("ldmatrix.sync.aligned.m8n8.x4.trans.shared.b16 {%0,%1,%2,%3}, [%4];" \
        : "=r"(r0),"=r"(r1),"=r"(r2),"=r"(r3) : "r"(addr))

__device__ __forceinline__ void hmma(float d[4], uint32_t a0, uint32_t a1, uint32_t a2, uint32_t a3,
                                     uint32_t b0, uint32_t b1) {
    asm volatile(
        "mma.sync.aligned.m16n8k16.row.col.f32.f16.f16.f32 "
        "{%0,%1,%2,%3}, {%4,%5,%6,%7}, {%8,%9}, {%0,%1,%2,%3};\n"
        : "+f"(d[0]), "+f"(d[1]), "+f"(d[2]), "+f"(d[3])
        : "r"(a0), "r"(a1), "r"(a2), "r"(a3), "r"(b0), "r"(b1));
}

__device__ __forceinline__ uint32_t smem_u32(const void* p) {
    uint32_t a;
    asm("{ .reg .u64 t; cvta.to.shared.u64 t, %1; cvt.u32.u64 %0, t; }" : "=r"(a) : "l"(p));
    return a;
}
__device__ __forceinline__ uint32_t pack2(float x, float y) {
    __half2 h = __floats2half2_rn(x, y);
    return *reinterpret_cast<uint32_t*>(&h);
}

__global__ void __launch_bounds__(NTHREADS, 1)
attn_h16_kernel(const float* __restrict__ Q, const float* __restrict__ K,
                const float* __restrict__ V, const float* __restrict__ Mask,
                float* __restrict__ Out) {
    extern __shared__ char smem[];
    const uint32_t sb = smem_u32(smem);
    float* maskT = (float*)(smem + MASK_B);
    float* lmT   = (float*)(smem + LM_B);
    float* Drow  = (float*)(smem + DROW_B);

    const int tid = threadIdx.x, w = tid >> 5, lane = tid & 31;
    const int g = lane >> 2, tig = lane & 3;
    const int b = blockIdx.y, l0 = blockIdx.x * BM;

    const float* Qb = Q + (size_t)b * CCH * LSEQ;
    const float* Kb = K + (size_t)b * CCH * LSEQ;
    const float* Vb = V + (size_t)b * CCH * LSEQ;
    const float* Mb = Mask + (size_t)b * LSEQ;

    // ---- stage Q once (fp16, /16): Qs[l][c], l=row ----
    {
        const float s16 = 0.0625f;
        #pragma unroll
        for (int i = 0; i < 8; i++) {
            int idx = i * NTHREADS + tid;   // 0..4095 float4s along l
            int c = idx >> 4, j = idx & 15;
            float4 v = *reinterpret_cast<const float4*>(Qb + (size_t)c * LSEQ + l0 + 4 * j);
            *(__half*)(smem + QS_B + ((4 * j + 0) * QSH + c) * 2) = __float2half_rn(v.x * s16);
            *(__half*)(smem + QS_B + ((4 * j + 1) * QSH + c) * 2) = __float2half_rn(v.y * s16);
            *(__half*)(smem + QS_B + ((4 * j + 2) * QSH + c) * 2) = __float2half_rn(v.z * s16);
            *(__half*)(smem + QS_B + ((4 * j + 3) * QSH + c) * 2) = __float2half_rn(v.w * s16);
        }
    }

    // warp tiles: S-GEMM 16x16 (4x4 grid); PV 64 rows x 16 ch
    const int R0 = 16 * (w & 3);
    const int C0 = 16 * (w >> 2);
    const int Cw = 16 * w;

    // ldmatrix lane base addresses
    const uint32_t aQ = sb + QS_B + ((R0 + (lane & 15)) * QSH + 8 * (lane >> 4)) * 2;
    const uint32_t aK = sb + KS_B + (((lane & 7) + 8 * ((lane >> 3) & 1)) * KVH
                                     + C0 + 8 * (lane >> 4)) * 2;
    const uint32_t aP = sb + PS_B + ((lane & 15) * PSH + 8 * (lane >> 4)) * 2;
    const uint32_t aV = sb + VS_B + ((Cw + (lane & 7) + 8 * (lane >> 4)) * KVH
                                     + 8 * ((lane >> 3) & 1)) * 2;

    float O[4][2][4];
    #pragma unroll
    for (int mt = 0; mt < 4; mt++)
        #pragma unroll
        for (int nt = 0; nt < 2; nt++)
            #pragma unroll
            for (int r = 0; r < 4; r++) O[mt][nt][r] = 0.0f;

    const int srow = tid >> 3;        // softmax row
    const int cq   = (tid & 7) * 8;   // softmax col base
    float den = 0.0f;

    __syncthreads();

    for (int t = 0; t < NTILES; t++) {
        const int m0 = t * BN;

        // ---- stage K tile (fp16): Ks[c][m] ----
        #pragma unroll
        for (int i = 0; i < 8; i++) {
            int idx = i * NTHREADS + tid;   // 0..4095 float4s (256c x 16 f4)
            int c = idx >> 4, j = idx & 15;
            float4 v = *reinterpret_cast<const float4*>(Kb + (size_t)c * LSEQ + m0 + 4 * j);
            uint2 h = make_uint2(pack2(v.x, v.y), pack2(v.z, v.w));
            *reinterpret_cast<uint2*>(smem + KS_B + (c * KVH + 4 * j) * 2) = h;
        }
        if (tid < 64) {
            float mk = Mb[m0 + tid];
            maskT[tid] = mk;
            lmT[tid] = __logf(mk + 1e-9f);
        }
        __syncthreads();

        // ---- S = (Q/16)^T K : 16 k16-steps, 2 HMMA each ----
        {
            float sacc[2][4];
            #pragma unroll
            for (int nt = 0; nt < 2; nt++)
                #pragma unroll
                for (int r = 0; r < 4; r++) sacc[nt][r] = 0.0f;

            uint32_t qa = aQ, ka = aK;
            #pragma unroll
            for (int s = 0; s < 16; s++) {
                uint32_t A0, A1, A2, A3, B0, B1, B2, B3;
                LDSM_X4(A0, A1, A2, A3, qa);
                LDSM_X4T(B0, B1, B2, B3, ka);
                hmma(sacc[0], A0, A1, A2, A3, B0, B1);
                hmma(sacc[1], A0, A1, A2, A3, B2, B3);
                qa += 32;            // +16 halves along k
                ka += 16 * KVH * 2;  // +16 k-rows
            }
            #pragma unroll
            for (int nt = 0; nt < 2; nt++) {
                int col = C0 + 8 * nt + 2 * tig;
                float* p0 = (float*)(smem + SS_B) + (R0 + g) * SSF + col;
                float* p1 = p0 + 8 * SSF;
                p0[0] = sacc[nt][0]; p0[1] = sacc[nt][1];
                p1[0] = sacc[nt][2]; p1[1] = sacc[nt][3];
            }
        }
        __syncthreads();   // S visible; K consumed

        // ---- stage V tile (fp16): Vs[c][m] ----
        #pragma unroll
        for (int i = 0; i < 8; i++) {
            int idx = i * NTHREADS + tid;
            int c = idx >> 4, j = idx & 15;
            float4 v = *reinterpret_cast<const float4*>(Vb + (size_t)c * LSEQ + m0 + 4 * j);
            uint2 h = make_uint2(pack2(v.x, v.y), pack2(v.z, v.w));
            *reinterpret_cast<uint2*>(smem + VS_B + (c * KVH + 4 * j) * 2) = h;
        }

        // ---- softmax (no max-subtraction; logits bounded ~6) ----
        {
            const float* srcp = (const float*)(smem + SS_B) + srow * SSF + cq;
            float4 s0 = *reinterpret_cast<const float4*>(srcp);
            float4 s1 = *reinterpret_cast<const float4*>(srcp + 4);
            const float* lmp = &lmT[cq];
            const float* mp  = &maskT[cq];
            float e0 = __expf(s0.x + lmp[0]), e1 = __expf(s0.y + lmp[1]);
            float e2 = __expf(s0.z + lmp[2]), e3 = __expf(s0.w + lmp[3]);
            float e4 = __expf(s1.x + lmp[4]), e5 = __expf(s1.y + lmp[5]);
            float e6 = __expf(s1.z + lmp[6]), e7 = __expf(s1.w + lmp[7]);
            den += ((e0 + e1) + (e2 + e3)) + ((e4 + e5) + (e6 + e7));
            uint4 pk;
            pk.x = pack2(e0 * mp[0], e1 * mp[1]);
            pk.y = pack2(e2 * mp[2], e3 * mp[3]);
            pk.z = pack2(e4 * mp[4], e5 * mp[5]);
            pk.w = pack2(e6 * mp[6], e7 * mp[7]);
            *reinterpret_cast<uint4*>(smem + PS_B + (srow * PSH + cq) * 2) = pk;
        }
        __syncthreads();   // P, V visible

        // ---- O += V * P^T : 4 k16-steps; warp = 64 rows x 16 ch ----
        #pragma unroll
        for (int s = 0; s < 4; s++) {
            uint32_t V0, V1, V2, V3;
            LDSM_X4(V0, V1, V2, V3, aV + s * 32);
            #pragma unroll
            for (int mt = 0; mt < 4; mt++) {
                uint32_t P0, P1, P2, P3;
                LDSM_X4(P0, P1, P2, P3, aP + mt * (16 * PSH * 2) + s * 32);
                hmma(O[mt][0], P0, P1, P2, P3, V0, V1);
                hmma(O[mt][1], P0, P1, P2, P3, V2, V3);
            }
        }
        __syncthreads();   // buffers free for next tile
    }

    // ---- reduce denominators (8 threads per row) ----
    den += __shfl_xor_sync(0xffffffffu, den, 1);
    den += __shfl_xor_sync(0xffffffffu, den, 2);
    den += __shfl_xor_sync(0xffffffffu, den, 4);
    if ((tid & 7) == 0) Drow[srow] = den;
    __syncthreads();

    // ---- epilogue: O/den, transpose via smem scratch, coalesced stores ----
    float* T = (float*)smem + w * 1040;   // 16 ch x 64 l, stride 65 (< DROW_B region)
    #pragma unroll
    for (int mt = 0; mt < 4; mt++) {
        float inv0 = 1.0f / Drow[16 * mt + g];
        float inv1 = 1.0f / Drow[16 * mt + 8 + g];
        #pragma unroll
        for (int nt = 0; nt < 2; nt++) {
            int c2 = 8 * nt + 2 * tig;
            T[(c2    ) * 65 + 16 * mt + g    ] = O[mt][nt][0] * inv0;
            T[(c2 + 1) * 65 + 16 * mt + g    ] = O[mt][nt][1] * inv0;
            T[(c2    ) * 65 + 16 * mt + g + 8] = O[mt][nt][2] * inv1;
            T[(c2 + 1) * 65 + 16 * mt + g + 8] = O[mt][nt][3] * inv1;
        }
    }
    __syncwarp();
    float* outw = Out + ((size_t)b * CCH + Cw) * LSEQ + l0;
    #pragma unroll 4
    for (int cl = 0; cl < 16; cl++) {
        float* orow = outw + (size_t)cl * LSEQ;
        orow[lane]      = T[cl * 65 + lane];
        orow[lane + 32] = T[cl * 65 + 32 + lane];
    }
}

extern "C" void kernel_launch(void* const* d_in, const int* in_sizes, int n_in,
                              void* d_out, int out_size) {
    (void)in_sizes; (void)n_in; (void)out_size;
    const float* Q = (const float*)d_in[0];
    const float* K = (const float*)d_in[1];
    const float* V = (const float*)d_in[2];
    const float* M = (const float*)d_in[3];
    float* O = (float*)d_out;

    cudaFuncSetAttribute(attn_h16_kernel,
                         cudaFuncAttributeMaxDynamicSharedMemorySize, SMEM_BYTES);
    dim3 grid(LSEQ / BM, BATCH);   // 32 x 16 = 512 CTAs
    attn_h16_kernel<<<grid, NTHREADS, SMEM_BYTES>>>(Q, K, V, M, O);
}